// round 14
// baseline (speedup 1.0000x reference)
#include <cuda_runtime.h>
#include <cuda_fp16.h>
#include <cstdint>

// ---------------- problem dims ----------------
#define BB 16
#define TT 64
#define LL 512
#define CC 64
#define HH 150
#define G3 450
#define HP 160            // padded h channels (10 k16-chunks per tap)

// K-chunk counts (k16 chunks)
#define XCH 20            // 5 taps * 4
#define HCH 50            // 5 taps * 10

// slab geometry
#define SLAB_ROWS 132     // 128 + 4 halo
#define RBX 128           // x slab row bytes (64 fp16)
#define RBH 384           // h slab row bytes (160 fp16 -> 24 units padded)
#define SLABX_B (SLAB_ROWS*RBX)   // 16896
#define SLABH_B (SLAB_ROWS*RBH)   // 50688
#define SM_TOTAL (2*SLABX_B + 2*SLABH_B)  // 135168

// ---------------- device scratch ----------------
__device__ float   g_h[BB*LL*HH];
__device__ __half  g_h_hi[BB*LL*HP];
__device__ __half  g_h_lo[BB*LL*HP];
__device__ __half  g_xs_hi[(size_t)BB*TT*LL*CC];
__device__ __half  g_xs_lo[(size_t)BB*TT*LL*CC];
__device__ float   g_gates[BB*LL*600];
__device__ int     g_sync[TT*64];          // per (t, mtb) arrival counters
// B in mma-fragment layout (single fp16): [chunk][n16(32)][lane(32)] uint4
__device__ uint4   g_bx[XCH*32*32];
__device__ uint4   g_bh[HCH*32*32];

// ---------------- helpers ----------------
__device__ __forceinline__ uint32_t smem_u32(const void* p) {
    uint32_t a;
    asm("{ .reg .u64 t; cvta.to.shared.u64 t, %1; cvt.u32.u64 %0, t; }" : "=r"(a) : "l"(p));
    return a;
}
__device__ __forceinline__ void ldsm4(uint32_t a[4], uint32_t addr) {
    asm volatile("ldmatrix.sync.aligned.m8n8.x4.shared.b16 {%0,%1,%2,%3}, [%4];"
                 : "=r"(a[0]), "=r"(a[1]), "=r"(a[2]), "=r"(a[3]) : "r"(addr));
}
__device__ __forceinline__ void mma_f16(float c[4], const uint32_t a[4], uint32_t b0, uint32_t b1) {
    asm volatile("mma.sync.aligned.m16n8k16.row.col.f32.f16.f16.f32 "
                 "{%0,%1,%2,%3}, {%4,%5,%6,%7}, {%8,%9}, {%0,%1,%2,%3};"
                 : "+f"(c[0]), "+f"(c[1]), "+f"(c[2]), "+f"(c[3])
                 : "r"(a[0]), "r"(a[1]), "r"(a[2]), "r"(a[3]), "r"(b0), "r"(b1));
}
__device__ __forceinline__ uint32_t pack_h2(float a, float b) {
    uint32_t lo = __half_as_ushort(__float2half(a));
    uint32_t hi = __half_as_ushort(__float2half(b));
    return lo | (hi << 16);
}

// ---------------- prep kernels ----------------
__global__ void init_h_kernel() {
    int i = blockIdx.x * blockDim.x + threadIdx.x;
    if (i < BB*LL*HH) g_h[i] = 0.f;
    if (i < BB*LL*HP) { g_h_hi[i] = __float2half(0.f); g_h_lo[i] = __float2half(0.f); }
    if (i < TT*64) g_sync[i] = 0;
}
__global__ void xs_split_kernel(const float* __restrict__ xs) {
    size_t i = (size_t)blockIdx.x * blockDim.x + threadIdx.x;
    if (i >= (size_t)BB*TT*LL*CC) return;
    float v = xs[i];
    __half hi = __float2half(v);
    g_xs_hi[i] = hi;
    g_xs_lo[i] = __float2half(v - __half2float(hi));
}
// pack ki into fragment layout (single fp16): k = d*64 + c, K=320
__global__ void bx_prep_kernel(const float* __restrict__ ki) {
    int idx = blockIdx.x * blockDim.x + threadIdx.x;
    if (idx >= XCH*32*32) return;
    int lane = idx & 31, n16 = (idx >> 5) & 31, ch = idx >> 10;
    int k0 = ch*16 + (lane & 3)*2;
    int na = n16*16 + (lane >> 2);
    float w[8];
#pragma unroll
    for (int h = 0; h < 2; h++) {
        int j = na + h*8;
#pragma unroll
        for (int kk = 0; kk < 4; kk++) {
            int k = k0 + (kk >> 1)*8 + (kk & 1);
            int d = k >> 6, c = k & 63;
            w[h*4 + kk] = (j < G3) ? ki[(d*CC + c)*G3 + j] : 0.f;
        }
    }
    g_bx[idx] = make_uint4(pack_h2(w[0],w[1]), pack_h2(w[2],w[3]),
                           pack_h2(w[4],w[5]), pack_h2(w[6],w[7]));
}
// pack kh (single fp16): k = d*160 + m, K=800
__global__ void bh_prep_kernel(const float* __restrict__ kh) {
    int idx = blockIdx.x * blockDim.x + threadIdx.x;
    if (idx >= HCH*32*32) return;
    int lane = idx & 31, n16 = (idx >> 5) & 31, ch = idx >> 10;
    int k0 = ch*16 + (lane & 3)*2;
    int na = n16*16 + (lane >> 2);
    float w[8];
#pragma unroll
    for (int h = 0; h < 2; h++) {
        int j = na + h*8;
#pragma unroll
        for (int kk = 0; kk < 4; kk++) {
            int k = k0 + (kk >> 1)*8 + (kk & 1);
            int d = k / HP, m = k - d*HP;
            w[h*4 + kk] = (j < G3 && m < HH) ? kh[(d*HH + m)*G3 + j] : 0.f;
        }
    }
    g_bh[idx] = make_uint4(pack_h2(w[0],w[1]), pack_h2(w[2],w[3]),
                           pack_h2(w[4],w[5]), pack_h2(w[6],w[7]));
}

// ---------------- the GEMM phase ----------------
// One conv (x or h) for one n16 tile, M=128. A = fp16 hi/lo split from
// swizzled smem slabs, B = single fp16 from fragment-packed global.
// 2 passes fused per chunk: (ah + al) * b  -> 4 HMMA per q.
template<int CPT, int RB>
__device__ __forceinline__ void run_phase(
    uint32_t sbh, uint32_t sbl,
    const uint4* __restrict__ B,
    float* acc, int n16g, int lane)
{
    const int rlow = lane & 15;
    const int r2   = lane >> 4;
    const uint4* b_p = B + n16g*32 + lane;
#pragma unroll 1
    for (int d = 0; d < 5; d++) {
#pragma unroll 1
        for (int cs = 0; cs < CPT; cs++) {
            const uint4 b = *b_p;  b_p += 1024;
            const int lu = cs*2 + r2;
#pragma unroll
            for (int q = 0; q < 8; q++) {
                uint32_t ah[4], al[4];
                const int row = d + q*16 + rlow;
                const uint32_t off = row*RB + (((lu ^ row) & 7) << 4) + ((lu & ~7) << 4);
                ldsm4(ah, sbh + off);
                ldsm4(al, sbl + off);
                float* A0 = acc + q*8;
                float* A1 = A0 + 4;
                mma_f16(A0, ah, b.x, b.y);
                mma_f16(A1, ah, b.z, b.w);
                mma_f16(A0, al, b.x, b.y);
                mma_f16(A1, al, b.z, b.w);
            }
        }
    }
}

// ---------------- step kernel (fused GRU gate) ----------------
__global__ __launch_bounds__(256, 1) void step_mma_kernel(int t)
{
    extern __shared__ char smem[];
    char* sxh = smem;
    char* sxl = smem + SLABX_B;
    char* shh = smem + 2*SLABX_B;
    char* shl = shh + SLABH_B;

    const int tid  = threadIdx.x;
    const int lane = tid & 31;
    const int wid  = tid >> 5;
    const int jhalf = blockIdx.x;          // 0..1
    const int mtb   = blockIdx.y;          // 0..63
    const int b  = mtb >> 2;
    const int l0 = (mtb & 3) * 128;

    // ---- fill x slab (hi+lo), swizzled: unit lu stored at lu^(row&7) ----
    for (int i = tid; i < SLAB_ROWS*8; i += 256) {
        const int s = i >> 3, lu = i & 7;
        const int lg = l0 - 2 + s;
        uint4 vh = make_uint4(0,0,0,0), vl = make_uint4(0,0,0,0);
        if (lg >= 0 && lg < LL) {
            const size_t base = ((size_t)(b*TT + t)*LL + lg)*CC + lu*8;
            vh = *(const uint4*)(g_xs_hi + base);
            vl = *(const uint4*)(g_xs_lo + base);
        }
        const int off = s*RBX + (((lu ^ s) & 7) << 4);
        *(uint4*)(sxh + off) = vh;
        *(uint4*)(sxl + off) = vl;
    }
    // ---- fill h slab (hi+lo), 20 units/row, padded row 24 units ----
    for (int i = tid; i < SLAB_ROWS*20; i += 256) {
        const int s = i / 20, lu = i - s*20;
        const int lg = l0 - 2 + s;
        uint4 vh = make_uint4(0,0,0,0), vl = make_uint4(0,0,0,0);
        if (lg >= 0 && lg < LL) {
            const size_t base = ((size_t)(b*LL + lg))*HP + lu*8;
            vh = *(const uint4*)(g_h_hi + base);
            vl = *(const uint4*)(g_h_lo + base);
        }
        const int off = s*RBH + ((lu & ~7) << 4) + (((lu ^ s) & 7) << 4);
        *(uint4*)(shh + off) = vh;
        *(uint4*)(shl + off) = vl;
    }
    __syncthreads();

    // Two n16 tile-groups per warp -> full j coverage [0, 464) across the grid.
#pragma unroll 1
    for (int g = 0; g < 2; g++) {
        const int n16g = jhalf*16 + g*8 + wid;   // 0..31
        if (n16g >= 29) continue;                // tiles 29..31 are pure zero padding

        float acc_i[64], acc_h[64];
#pragma unroll
        for (int q = 0; q < 64; q++) { acc_i[q] = 0.f; acc_h[q] = 0.f; }

        run_phase<4,  RBX>(smem_u32(sxh), smem_u32(sxl), g_bx, acc_i, n16g, lane);
        run_phase<10, RBH>(smem_u32(shh), smem_u32(shl), g_bh, acc_h, n16g, lane);

        // ---- epilogue: write gate pre-activations ----
        const int row_in = lane >> 2;
        const int col0   = (lane & 3)*2;
        const int jb     = n16g*16;
#pragma unroll
        for (int mt = 0; mt < 8; mt++) {
#pragma unroll
            for (int rr = 0; rr < 2; rr++) {
                const int l = l0 + mt*16 + row_in + rr*8;
                float* grow = g_gates + (size_t)(b*LL + l)*600;
#pragma unroll
                for (int n8 = 0; n8 < 2; n8++) {
#pragma unroll
                    for (int cc = 0; cc < 2; cc++) {
                        const int j  = jb + n8*8 + col0 + cc;
                        const float vi = acc_i[mt*8 + n8*4 + rr*2 + cc];
                        const float vh = acc_h[mt*8 + n8*4 + rr*2 + cc];
                        if (j < 300)      grow[j] = vi + vh;
                        else if (j < G3) { grow[j] = vi; grow[j + 150] = vh; }
                    }
                }
            }
        }
    }

    // ---- cross-CTA pair sync + fused GRU gate update ----
    __threadfence();
    __syncthreads();
    int* flag = &g_sync[t*64 + mtb];
    if (tid == 0) atomicAdd(flag, 1);
    if (jhalf == 0) {
        if (tid == 0) { while (atomicAdd(flag, 0) < 2) { } }
        __syncthreads();
        // gate update for rows [l0, l0+128) of batch b
        for (int i = tid; i < 128*HH; i += 256) {
            const int lr = i / HH, m = i - lr*HH;
            const size_t bl = (size_t)(b*LL + l0 + lr);
            const float* G = g_gates + bl*600;
            float r = 1.f / (1.f + __expf(-G[m]));
            float z = 1.f / (1.f + __expf(-(G[150 + m])));
            float n = tanhf(G[300 + m] + r * G[450 + m]);
            float h = (1.f - z) * n + z * g_h[bl*HH + m];
            g_h[bl*HH + m] = h;
            __half hi = __float2half(h);
            g_h_hi[bl*HP + m] = hi;
            g_h_lo[bl*HP + m] = __float2half(h - __half2float(hi));
        }
    }
}

// ---------------- head ----------------
__global__ void head_kernel(const float* __restrict__ W1, const float* __restrict__ b1,
                            const float* __restrict__ W2, const float* __restrict__ b2,
                            float* __restrict__ out)
{
    __shared__ float hv[HH];
    __shared__ float hd[HH];
    const int bl  = blockIdx.x;
    const int tid = threadIdx.x;
    if (tid < HH) hv[tid] = g_h[(size_t)bl*HH + tid];
    __syncthreads();
    if (tid < HH) {
        float s = b1[tid];
#pragma unroll 5
        for (int m = 0; m < HH; m++) s += hv[m] * W1[m*HH + tid];
        hd[tid] = s / (1.f + __expf(-s));
    }
    __syncthreads();
    if (tid < 24) {
        float s = b2[tid];
#pragma unroll 5
        for (int m = 0; m < HH; m++) s += hd[m] * W2[m*24 + tid];
        out[(size_t)bl*24 + tid] = s;
    }
}

extern "C" void kernel_launch(void* const* d_in, const int* in_sizes, int n_in,
                              void* d_out, int out_size)
{
    const float* xs = (const float*)d_in[0];
    const float* ki = (const float*)d_in[1];
    const float* kh = (const float*)d_in[2];
    const float* W1 = (const float*)d_in[3];
    const float* b1 = (const float*)d_in[4];
    const float* W2 = (const float*)d_in[5];
    const float* b2 = (const float*)d_in[6];
    float* out = (float*)d_out;

    cudaFuncSetAttribute(step_mma_kernel, cudaFuncAttributeMaxDynamicSharedMemorySize, SM_TOTAL);

    init_h_kernel<<<(BB*LL*HP + 255)/256, 256>>>();
    const size_t nxs = (size_t)BB*TT*LL*CC;
    xs_split_kernel<<<(unsigned)((nxs + 255)/256), 256>>>(xs);
    bx_prep_kernel<<<(XCH*32*32 + 255)/256, 256>>>(ki);
    bh_prep_kernel<<<(HCH*32*32 + 255)/256, 256>>>(kh);

    dim3 grid(2, 64);   // j-half x M-tiles
    for (int t = 0; t < TT; t++) {
        step_mma_kernel<<<grid, 256, SM_TOTAL>>>(t);
    }

    head_kernel<<<BB*LL, 160>>>(W1, b1, W2, b2, out);
}

// round 15
// speedup vs baseline: 1.9095x; 1.9095x over previous
#include <cuda_runtime.h>
#include <cuda_fp16.h>
#include <cstdint>

// ---------------- problem dims ----------------
#define BB 16
#define TT 64
#define LL 512
#define CC 64
#define HH 150
#define G3 450
#define HP 160            // padded h channels (10 k16-chunks per tap)

// K-chunk counts (k16 chunks)
#define XCH 20            // 5 taps * 4
#define HCH 50            // 5 taps * 10

// slab geometry
#define SLAB_ROWS 132     // 128 + 4 halo
#define RBX 128           // x slab row bytes (64 fp16)
#define RBH 384           // h slab row bytes (160 fp16 -> 24 units padded)
#define SLABX_B (SLAB_ROWS*RBX)   // 16896
#define SLABH_B (SLAB_ROWS*RBH)   // 50688
#define SM_TOTAL (2*SLABX_B + 2*SLABH_B)  // 135168

// ---------------- device scratch ----------------
__device__ float   g_h[BB*LL*HH];
__device__ __half  g_h_hi[BB*LL*HP];
__device__ __half  g_h_lo[BB*LL*HP];
__device__ __half  g_xs_hi[(size_t)BB*TT*LL*CC];
__device__ __half  g_xs_lo[(size_t)BB*TT*LL*CC];
__device__ float   g_gates[BB*LL*600];
// B in mma-fragment layout (single fp16): [chunk][n16(32)][lane(32)] uint4
__device__ uint4   g_bx[XCH*32*32];
__device__ uint4   g_bh[HCH*32*32];

// ---------------- helpers ----------------
__device__ __forceinline__ uint32_t smem_u32(const void* p) {
    uint32_t a;
    asm("{ .reg .u64 t; cvta.to.shared.u64 t, %1; cvt.u32.u64 %0, t; }" : "=r"(a) : "l"(p));
    return a;
}
__device__ __forceinline__ void ldsm4(uint32_t a[4], uint32_t addr) {
    asm volatile("ldmatrix.sync.aligned.m8n8.x4.shared.b16 {%0,%1,%2,%3}, [%4];"
                 : "=r"(a[0]), "=r"(a[1]), "=r"(a[2]), "=r"(a[3]) : "r"(addr));
}
__device__ __forceinline__ void mma_f16(float c[4], const uint32_t a[4], uint32_t b0, uint32_t b1) {
    asm volatile("mma.sync.aligned.m16n8k16.row.col.f32.f16.f16.f32 "
                 "{%0,%1,%2,%3}, {%4,%5,%6,%7}, {%8,%9}, {%0,%1,%2,%3};"
                 : "+f"(c[0]), "+f"(c[1]), "+f"(c[2]), "+f"(c[3])
                 : "r"(a[0]), "r"(a[1]), "r"(a[2]), "r"(a[3]), "r"(b0), "r"(b1));
}
__device__ __forceinline__ uint32_t pack_h2(float a, float b) {
    uint32_t lo = __half_as_ushort(__float2half(a));
    uint32_t hi = __half_as_ushort(__float2half(b));
    return lo | (hi << 16);
}

// ---------------- prep kernels ----------------
__global__ void init_h_kernel() {
    int i = blockIdx.x * blockDim.x + threadIdx.x;
    if (i < BB*LL*HH) g_h[i] = 0.f;
    if (i < BB*LL*HP) { g_h_hi[i] = __float2half(0.f); g_h_lo[i] = __float2half(0.f); }
}
__global__ void xs_split_kernel(const float* __restrict__ xs) {
    size_t i = (size_t)blockIdx.x * blockDim.x + threadIdx.x;
    if (i >= (size_t)BB*TT*LL*CC) return;
    float v = xs[i];
    __half hi = __float2half(v);
    g_xs_hi[i] = hi;
    g_xs_lo[i] = __float2half(v - __half2float(hi));
}
// pack ki into fragment layout (single fp16): k = d*64 + c, K=320
__global__ void bx_prep_kernel(const float* __restrict__ ki) {
    int idx = blockIdx.x * blockDim.x + threadIdx.x;
    if (idx >= XCH*32*32) return;
    int lane = idx & 31, n16 = (idx >> 5) & 31, ch = idx >> 10;
    int k0 = ch*16 + (lane & 3)*2;
    int na = n16*16 + (lane >> 2);
    float w[8];
#pragma unroll
    for (int h = 0; h < 2; h++) {
        int j = na + h*8;
#pragma unroll
        for (int kk = 0; kk < 4; kk++) {
            int k = k0 + (kk >> 1)*8 + (kk & 1);
            int d = k >> 6, c = k & 63;
            w[h*4 + kk] = (j < G3) ? ki[(d*CC + c)*G3 + j] : 0.f;
        }
    }
    g_bx[idx] = make_uint4(pack_h2(w[0],w[1]), pack_h2(w[2],w[3]),
                           pack_h2(w[4],w[5]), pack_h2(w[6],w[7]));
}
// pack kh (single fp16): k = d*160 + m, K=800
__global__ void bh_prep_kernel(const float* __restrict__ kh) {
    int idx = blockIdx.x * blockDim.x + threadIdx.x;
    if (idx >= HCH*32*32) return;
    int lane = idx & 31, n16 = (idx >> 5) & 31, ch = idx >> 10;
    int k0 = ch*16 + (lane & 3)*2;
    int na = n16*16 + (lane >> 2);
    float w[8];
#pragma unroll
    for (int h = 0; h < 2; h++) {
        int j = na + h*8;
#pragma unroll
        for (int kk = 0; kk < 4; kk++) {
            int k = k0 + (kk >> 1)*8 + (kk & 1);
            int d = k / HP, m = k - d*HP;
            w[h*4 + kk] = (j < G3 && m < HH) ? kh[(d*HH + m)*G3 + j] : 0.f;
        }
    }
    g_bh[idx] = make_uint4(pack_h2(w[0],w[1]), pack_h2(w[2],w[3]),
                           pack_h2(w[4],w[5]), pack_h2(w[6],w[7]));
}

// ---------------- the GEMM phase ----------------
// One conv (x or h) for one n16 tile, M=128. A = fp16 hi/lo split from
// swizzled smem slabs, B = single fp16 from fragment-packed global.
// 2 passes fused per chunk: (ah + al) * b -> 4 HMMA per q.
template<int CPT, int RB>
__device__ __forceinline__ void run_phase(
    uint32_t sbh, uint32_t sbl,
    const uint4* __restrict__ B,
    float* acc, int n16g, int lane)
{
    const int rlow = lane & 15;
    const int r2   = lane >> 4;
    const uint4* b_p = B + n16g*32 + lane;
#pragma unroll 1
    for (int d = 0; d < 5; d++) {
#pragma unroll 1
        for (int cs = 0; cs < CPT; cs++) {
            const uint4 b = *b_p;  b_p += 1024;
            const int lu = cs*2 + r2;
#pragma unroll
            for (int q = 0; q < 8; q++) {
                uint32_t ah[4], al[4];
                const int row = d + q*16 + rlow;
                const uint32_t off = row*RB + (((lu ^ row) & 7) << 4) + ((lu & ~7) << 4);
                ldsm4(ah, sbh + off);
                ldsm4(al, sbl + off);
                float* A0 = acc + q*8;
                float* A1 = A0 + 4;
                mma_f16(A0, ah, b.x, b.y);
                mma_f16(A1, ah, b.z, b.w);
                mma_f16(A0, al, b.x, b.y);
                mma_f16(A1, al, b.z, b.w);
            }
        }
    }
}

// ---------------- step kernel (R8 structure: 256 thr, 2 tiles/warp) ----------------
__global__ __launch_bounds__(256, 1) void step_mma_kernel(int t)
{
    extern __shared__ char smem[];
    char* sxh = smem;
    char* sxl = smem + SLABX_B;
    char* shh = smem + 2*SLABX_B;
    char* shl = shh + SLABH_B;

    const int tid  = threadIdx.x;
    const int lane = tid & 31;
    const int wid  = tid >> 5;
    const int jhalf = blockIdx.x;          // 0..1
    const int mtb   = blockIdx.y;          // 0..63
    const int b  = mtb >> 2;
    const int l0 = (mtb & 3) * 128;

    // ---- fill x slab (hi+lo), swizzled: unit lu stored at lu^(row&7) ----
    for (int i = tid; i < SLAB_ROWS*8; i += 256) {
        const int s = i >> 3, lu = i & 7;
        const int lg = l0 - 2 + s;
        uint4 vh = make_uint4(0,0,0,0), vl = make_uint4(0,0,0,0);
        if (lg >= 0 && lg < LL) {
            const size_t base = ((size_t)(b*TT + t)*LL + lg)*CC + lu*8;
            vh = *(const uint4*)(g_xs_hi + base);
            vl = *(const uint4*)(g_xs_lo + base);
        }
        const int off = s*RBX + (((lu ^ s) & 7) << 4);
        *(uint4*)(sxh + off) = vh;
        *(uint4*)(sxl + off) = vl;
    }
    // ---- fill h slab (hi+lo), 20 units/row, padded row 24 units ----
    for (int i = tid; i < SLAB_ROWS*20; i += 256) {
        const int s = i / 20, lu = i - s*20;
        const int lg = l0 - 2 + s;
        uint4 vh = make_uint4(0,0,0,0), vl = make_uint4(0,0,0,0);
        if (lg >= 0 && lg < LL) {
            const size_t base = ((size_t)(b*LL + lg))*HP + lu*8;
            vh = *(const uint4*)(g_h_hi + base);
            vl = *(const uint4*)(g_h_lo + base);
        }
        const int off = s*RBH + ((lu & ~7) << 4) + (((lu ^ s) & 7) << 4);
        *(uint4*)(shh + off) = vh;
        *(uint4*)(shl + off) = vl;
    }
    __syncthreads();

    // Two n16 tile-groups per warp -> full j coverage [0, 464) across the grid.
#pragma unroll 1
    for (int g = 0; g < 2; g++) {
        const int n16g = jhalf*16 + g*8 + wid;   // 0..31
        if (n16g >= 29) continue;                // tiles 29..31 are pure zero padding

        float acc_i[64], acc_h[64];
#pragma unroll
        for (int q = 0; q < 64; q++) { acc_i[q] = 0.f; acc_h[q] = 0.f; }

        run_phase<4,  RBX>(smem_u32(sxh), smem_u32(sxl), g_bx, acc_i, n16g, lane);
        run_phase<10, RBH>(smem_u32(shh), smem_u32(shl), g_bh, acc_h, n16g, lane);

        // ---- epilogue: write gate pre-activations ----
        const int row_in = lane >> 2;
        const int col0   = (lane & 3)*2;
        const int jb     = n16g*16;
#pragma unroll
        for (int mt = 0; mt < 8; mt++) {
#pragma unroll
            for (int rr = 0; rr < 2; rr++) {
                const int l = l0 + mt*16 + row_in + rr*8;
                float* grow = g_gates + (size_t)(b*LL + l)*600;
#pragma unroll
                for (int n8 = 0; n8 < 2; n8++) {
#pragma unroll
                    for (int cc = 0; cc < 2; cc++) {
                        const int j  = jb + n8*8 + col0 + cc;
                        const float vi = acc_i[mt*8 + n8*4 + rr*2 + cc];
                        const float vh = acc_h[mt*8 + n8*4 + rr*2 + cc];
                        if (j < 300)      grow[j] = vi + vh;
                        else if (j < G3) { grow[j] = vi; grow[j + 150] = vh; }
                    }
                }
            }
        }
    }
}

// ---------------- GRU gate update ----------------
__global__ void gate_kernel() {
    int idx = blockIdx.x * blockDim.x + threadIdx.x;
    if (idx >= BB*LL*HH) return;
    int bl = idx / HH;
    int m  = idx - bl*HH;
    const float* G = g_gates + (size_t)bl * 600;
    float r = 1.f / (1.f + __expf(-G[m]));
    float z = 1.f / (1.f + __expf(-(G[150 + m])));
    float n = tanhf(G[300 + m] + r * G[450 + m]);
    float h = (1.f - z) * n + z * g_h[idx];
    g_h[idx] = h;
    __half hi = __float2half(h);
    g_h_hi[(size_t)bl*HP + m] = hi;
    g_h_lo[(size_t)bl*HP + m] = __float2half(h - __half2float(hi));
}

// ---------------- head ----------------
__global__ void head_kernel(const float* __restrict__ W1, const float* __restrict__ b1,
                            const float* __restrict__ W2, const float* __restrict__ b2,
                            float* __restrict__ out)
{
    __shared__ float hv[HH];
    __shared__ float hd[HH];
    const int bl  = blockIdx.x;
    const int tid = threadIdx.x;
    if (tid < HH) hv[tid] = g_h[(size_t)bl*HH + tid];
    __syncthreads();
    if (tid < HH) {
        float s = b1[tid];
#pragma unroll 5
        for (int m = 0; m < HH; m++) s += hv[m] * W1[m*HH + tid];
        hd[tid] = s / (1.f + __expf(-s));
    }
    __syncthreads();
    if (tid < 24) {
        float s = b2[tid];
#pragma unroll 5
        for (int m = 0; m < HH; m++) s += hd[m] * W2[m*24 + tid];
        out[(size_t)bl*24 + tid] = s;
    }
}

extern "C" void kernel_launch(void* const* d_in, const int* in_sizes, int n_in,
                              void* d_out, int out_size)
{
    const float* xs = (const float*)d_in[0];
    const float* ki = (const float*)d_in[1];
    const float* kh = (const float*)d_in[2];
    const float* W1 = (const float*)d_in[3];
    const float* b1 = (const float*)d_in[4];
    const float* W2 = (const float*)d_in[5];
    const float* b2 = (const float*)d_in[6];
    float* out = (float*)d_out;

    cudaFuncSetAttribute(step_mma_kernel, cudaFuncAttributeMaxDynamicSharedMemorySize, SM_TOTAL);

    init_h_kernel<<<(BB*LL*HP + 255)/256, 256>>>();
    const size_t nxs = (size_t)BB*TT*LL*CC;
    xs_split_kernel<<<(unsigned)((nxs + 255)/256), 256>>>(xs);
    bx_prep_kernel<<<(XCH*32*32 + 255)/256, 256>>>(ki);
    bh_prep_kernel<<<(HCH*32*32 + 255)/256, 256>>>(kh);

    dim3 grid(2, 64);   // j-half x M-tiles
    for (int t = 0; t < TT; t++) {
        step_mma_kernel<<<grid, 256, SM_TOTAL>>>(t);
        gate_kernel<<<(BB*LL*HH + 255)/256, 256>>>();
    }

    head_kernel<<<BB*LL, 160>>>(W1, b1, W2, b2, out);
}